// round 14
// baseline (speedup 1.0000x reference)
#include <cuda_runtime.h>
#include <cuda_bf16.h>
#include <stdint.h>
#include <math.h>

// ---------------------------------------------------------------------------
// Problem constants
// ---------------------------------------------------------------------------
#define NNODES 50000
#define NEDGES 1000000
#define FD     256
#define NC     300
#define NCP    320   // NC padded to multiple of 32
#define ED     64

typedef unsigned short u16;
typedef unsigned int   u32;

// ---------------------------------------------------------------------------
// Scratch (device globals — no allocation allowed)
// All activations/weights stored as split bf16 "planes": hi plane + lo plane,
// value = float(hi) + float(lo)  (≈ fp32 with 16-bit mantissa, err ~2^-17).
// ---------------------------------------------------------------------------
__device__ u16 g_cont_h[NNODES * NCP], g_cont_l[NNODES * NCP];
__device__ u16 g_c_h[NNODES * NCP],    g_c_l[NNODES * NCP];
__device__ u16 g_e_h[NNODES * ED],     g_e_l[NNODES * ED];
__device__ u16 g_h_h[NNODES * FD],     g_h_l[NNODES * FD];
__device__ u16 g_t_h[NNODES * FD],     g_t_l[NNODES * FD];
__device__ u16 g_g_h[NNODES * FD],     g_g_l[NNODES * FD];

// weight-plane offsets (u16 elements)
#define WP1   0
#define WP2   96000              // + 300*320
#define WEXP  177920             // + 256*320
#define WCONV 194304             // + 256*64
#define WO1   587520             // + 3*256*512
#define WO2   718592             // + 2*256*256
#define WTOT  849664             // + 2*256*256
__device__ u16 g_w_h[WTOT], g_w_l[WTOT];

__device__ int g_deg[NNODES];
__device__ int g_off[NNODES + 1];
__device__ int g_cur[NNODES];
__device__ int g_csr[NEDGES];

// ---------------------------------------------------------------------------
// Helpers
// ---------------------------------------------------------------------------
__device__ __forceinline__ u32 smem_u32(const void* p) {
    u32 a;
    asm("{ .reg .u64 t; cvta.to.shared.u64 t, %1; cvt.u32.u64 %0, t; }" : "=r"(a) : "l"(p));
    return a;
}
__device__ __forceinline__ void splitf(float x, u16& h, u16& l) {
    __nv_bfloat16 hb = __float2bfloat16(x);
    float hf = __bfloat162float(hb);
    __nv_bfloat16 lb = __float2bfloat16(x - hf);
    h = __bfloat16_as_ushort(hb);
    l = __bfloat16_as_ushort(lb);
}
// bf16 bits -> fp32 (low / high half of a packed u32) — pure bit ops
__device__ __forceinline__ float bflo(u32 u) { return __uint_as_float(u << 16); }
__device__ __forceinline__ float bfhi(u32 u) { return __uint_as_float(u & 0xFFFF0000u); }

__device__ __forceinline__ void ldsm_x4(u32& r0, u32& r1, u32& r2, u32& r3, u32 addr) {
    asm volatile("ldmatrix.sync.aligned.m8n8.x4.shared.b16 {%0,%1,%2,%3}, [%4];"
                 : "=r"(r0), "=r"(r1), "=r"(r2), "=r"(r3) : "r"(addr));
}
__device__ __forceinline__ void mma16816(float* c, u32 a0, u32 a1, u32 a2, u32 a3,
                                         u32 b0, u32 b1) {
    asm volatile("mma.sync.aligned.m16n8k16.row.col.f32.bf16.bf16.f32 "
                 "{%0,%1,%2,%3}, {%4,%5,%6,%7}, {%8,%9}, {%0,%1,%2,%3};"
                 : "+f"(c[0]), "+f"(c[1]), "+f"(c[2]), "+f"(c[3])
                 : "r"(a0), "r"(a1), "r"(a2), "r"(a3), "r"(b0), "r"(b1));
}
// cp.async with zfill mask: pointer is ALWAYS in-bounds (caller clamps row),
// src-size=0 only zero-fills.
__device__ __forceinline__ void cp16(u32 dst, const void* src, int valid) {
    asm volatile("cp.async.cg.shared.global [%0], [%1], 16, %2;"
                 :: "r"(dst), "l"(src), "r"(valid ? 16 : 0));
}

// ---------------------------------------------------------------------------
// Prep: split fp32 matrix (rows x sc) into hi/lo planes (rows x dc, zero-pad),
// optional row gather.
// ---------------------------------------------------------------------------
__global__ void split_kernel(const float* __restrict__ src, int rows, int sc, int dc,
                             u16* __restrict__ dh, u16* __restrict__ dl,
                             const int* __restrict__ gather) {
    int i = blockIdx.x * blockDim.x + threadIdx.x;
    if (i >= rows * dc) return;
    int r = i / dc, c = i - r * dc;
    float v = 0.f;
    if (c < sc) {
        int rr = gather ? gather[r] : r;
        v = src[(size_t)rr * sc + c];
    }
    u16 h, l;
    splitf(v, h, l);
    dh[i] = h;
    dl[i] = l;
}

// ---------------------------------------------------------------------------
// CSR build kernels
// ---------------------------------------------------------------------------
__global__ void zero_int_kernel(int* p, int n) {
    int i = blockIdx.x * blockDim.x + threadIdx.x;
    if (i < n) p[i] = 0;
}
__global__ void deg_kernel(const int* __restrict__ dst, int* __restrict__ deg, int e) {
    int i = blockIdx.x * blockDim.x + threadIdx.x;
    if (i < e) atomicAdd(&deg[dst[i]], 1);
}
__global__ void scan_kernel(const int* __restrict__ deg, int* __restrict__ off,
                            int* __restrict__ cur, int n) {
    __shared__ int sh[1024];
    __shared__ int carry;
    int tid = threadIdx.x;
    if (tid == 0) carry = 0;
    __syncthreads();
    for (int base = 0; base < n; base += 1024) {
        int i = base + tid;
        int v = (i < n) ? deg[i] : 0;
        sh[tid] = v;
        __syncthreads();
        #pragma unroll
        for (int s = 1; s < 1024; s <<= 1) {
            int t = (tid >= s) ? sh[tid - s] : 0;
            __syncthreads();
            sh[tid] += t;
            __syncthreads();
        }
        int excl = sh[tid] - v + carry;
        if (i < n) { off[i] = excl; cur[i] = excl; }
        __syncthreads();
        if (tid == 0) carry += sh[1023];
        __syncthreads();
    }
    if (tid == 0) off[n] = carry;
}
__global__ void fill_kernel(const int* __restrict__ src, const int* __restrict__ dst,
                            int* __restrict__ cur, int* __restrict__ csr, int e) {
    int i = blockIdx.x * blockDim.x + threadIdx.x;
    if (i < e) {
        int d = dst[i];
        int p = atomicAdd(&cur[d], 1);
        csr[p] = src[i];
    }
}

// ---------------------------------------------------------------------------
// Aggregation on planes: o[n,:] = (sum_{s in CSR[n]} h[s,:]) / max(deg,1)
// Warp per node, lane owns 8 columns. 4-neighbor unroll for MLP.
// ---------------------------------------------------------------------------
#define ACC8(hv, lv)                                                   \
    { acc[0] += bflo(hv.x) + bflo(lv.x); acc[1] += bfhi(hv.x) + bfhi(lv.x); \
      acc[2] += bflo(hv.y) + bflo(lv.y); acc[3] += bfhi(hv.y) + bfhi(lv.y); \
      acc[4] += bflo(hv.z) + bflo(lv.z); acc[5] += bfhi(hv.z) + bfhi(lv.z); \
      acc[6] += bflo(hv.w) + bflo(lv.w); acc[7] += bfhi(hv.w) + bfhi(lv.w); }

__global__ void agg_pl(const u16* __restrict__ hh, const u16* __restrict__ hl,
                       const int* __restrict__ off, const int* __restrict__ csr,
                       u16* __restrict__ oh, u16* __restrict__ ol, int n) {
    int w = (blockIdx.x * blockDim.x + threadIdx.x) >> 5;
    int lane = threadIdx.x & 31;
    if (w >= n) return;
    int beg = off[w], end = off[w + 1];
    size_t lo8 = (size_t)lane * 8;

    float acc[8];
    #pragma unroll
    for (int i = 0; i < 8; i++) acc[i] = 0.f;

    int j = beg;
    for (; j + 3 < end; j += 4) {
        int s0 = csr[j], s1 = csr[j + 1], s2 = csr[j + 2], s3 = csr[j + 3];
        uint4 h0 = *(const uint4*)(hh + (size_t)s0 * FD + lo8);
        uint4 l0 = *(const uint4*)(hl + (size_t)s0 * FD + lo8);
        uint4 h1 = *(const uint4*)(hh + (size_t)s1 * FD + lo8);
        uint4 l1 = *(const uint4*)(hl + (size_t)s1 * FD + lo8);
        uint4 h2 = *(const uint4*)(hh + (size_t)s2 * FD + lo8);
        uint4 l2 = *(const uint4*)(hl + (size_t)s2 * FD + lo8);
        uint4 h3 = *(const uint4*)(hh + (size_t)s3 * FD + lo8);
        uint4 l3 = *(const uint4*)(hl + (size_t)s3 * FD + lo8);
        ACC8(h0, l0);
        ACC8(h1, l1);
        ACC8(h2, l2);
        ACC8(h3, l3);
    }
    for (; j < end; j++) {
        int s0 = csr[j];
        uint4 h0 = *(const uint4*)(hh + (size_t)s0 * FD + lo8);
        uint4 l0 = *(const uint4*)(hl + (size_t)s0 * FD + lo8);
        ACC8(h0, l0);
    }
    int d = end - beg;
    float inv = 1.f / (float)(d > 0 ? d : 1);

    u16 sh[8], sl[8];
    #pragma unroll
    for (int i = 0; i < 8; i++) splitf(acc[i] * inv, sh[i], sl[i]);
    uint4 vh, vl;
    vh.x = sh[0] | ((u32)sh[1] << 16); vl.x = sl[0] | ((u32)sl[1] << 16);
    vh.y = sh[2] | ((u32)sh[3] << 16); vl.y = sl[2] | ((u32)sl[3] << 16);
    vh.z = sh[4] | ((u32)sh[5] << 16); vl.z = sl[4] | ((u32)sl[5] << 16);
    vh.w = sh[6] | ((u32)sh[7] << 16); vl.w = sl[6] | ((u32)sl[7] << 16);
    *(uint4*)(oh + (size_t)w * FD + lo8) = vh;
    *(uint4*)(ol + (size_t)w * FD + lo8) = vl;
}

// ---------------------------------------------------------------------------
// Row L2 normalize on planes. If of != null, write fp32 there instead.
// ---------------------------------------------------------------------------
__global__ void norm_pl(const u16* __restrict__ th, const u16* __restrict__ tl,
                        u16* __restrict__ oh, u16* __restrict__ ol,
                        float* __restrict__ of, int n) {
    int w = (blockIdx.x * blockDim.x + threadIdx.x) >> 5;
    int lane = threadIdx.x & 31;
    if (w >= n) return;
    size_t lo8 = (size_t)lane * 8;
    uint4 hv = *(const uint4*)(th + (size_t)w * FD + lo8);
    uint4 lv = *(const uint4*)(tl + (size_t)w * FD + lo8);
    float x[8];
    x[0] = bflo(hv.x) + bflo(lv.x); x[1] = bfhi(hv.x) + bfhi(lv.x);
    x[2] = bflo(hv.y) + bflo(lv.y); x[3] = bfhi(hv.y) + bfhi(lv.y);
    x[4] = bflo(hv.z) + bflo(lv.z); x[5] = bfhi(hv.z) + bfhi(lv.z);
    x[6] = bflo(hv.w) + bflo(lv.w); x[7] = bfhi(hv.w) + bfhi(lv.w);
    float s = 0.f;
    #pragma unroll
    for (int i = 0; i < 8; i++) s += x[i] * x[i];
    #pragma unroll
    for (int o = 16; o; o >>= 1) s += __shfl_xor_sync(0xFFFFFFFFu, s, o);
    float inv = 1.f / fmaxf(sqrtf(s), 1e-6f);
    #pragma unroll
    for (int i = 0; i < 8; i++) x[i] *= inv;

    if (of) {
        float4 a = make_float4(x[0], x[1], x[2], x[3]);
        float4 b = make_float4(x[4], x[5], x[6], x[7]);
        *(float4*)(of + (size_t)w * FD + lo8)     = a;
        *(float4*)(of + (size_t)w * FD + lo8 + 4) = b;
    } else {
        u16 sh[8], sl[8];
        #pragma unroll
        for (int i = 0; i < 8; i++) splitf(x[i], sh[i], sl[i]);
        uint4 vh, vl;
        vh.x = sh[0] | ((u32)sh[1] << 16); vl.x = sl[0] | ((u32)sl[1] << 16);
        vh.y = sh[2] | ((u32)sh[3] << 16); vl.y = sl[2] | ((u32)sl[3] << 16);
        vh.z = sh[4] | ((u32)sh[5] << 16); vl.z = sl[4] | ((u32)sl[5] << 16);
        vh.w = sh[6] | ((u32)sh[7] << 16); vl.w = sl[6] | ((u32)sl[7] << 16);
        *(uint4*)(oh + (size_t)w * FD + lo8) = vh;
        *(uint4*)(ol + (size_t)w * FD + lo8) = vl;
    }
}

// ---------------------------------------------------------------------------
// Plane GEMM (split-bf16, 3-pass: AhBh + AhBl + AlBh, fp32 accum):
//   C[m,n] = act( sum_k A[m,k]*B[n,k] + bias[n] ) (+ addin) -> hi/lo planes
// A concat: k < K0 from (Ah,Al) stride K0; k >= K0 from (A2h,A2l) stride K-K0.
// B planes stride K. Tile 128x128, K-chunk 64, 2-stage cp.async pipeline.
// SMEM tiles: 128 rows x 64 bf16, row stride 144B (conflict-free ldmatrix:
// row-start mod 128B = 16r -> 8-row period covers all 16B banks).
// OOB rows: pointer clamped in-bounds, cp.async zfill writes zeros.
// ---------------------------------------------------------------------------
#define TS   18432            // one tile: 128*144 bytes
#define STG  (4 * TS)         // Ah,Al,Bh,Bl per stage = 73728
#define GSM  (2 * STG)        // 147456 bytes dynamic smem
#define ROWB 144

__global__ void __launch_bounds__(256)
pgemm(const u16* __restrict__ Ah, const u16* __restrict__ Al,
      const u16* __restrict__ A2h, const u16* __restrict__ A2l, int K0,
      const u16* __restrict__ Bh, const u16* __restrict__ Bl,
      const float* __restrict__ bias,
      const u16* __restrict__ addh, const u16* __restrict__ addl,
      u16* __restrict__ Ch, u16* __restrict__ Cl, int Cs,
      int M, int Nn, int K, int do_lrelu) {
    extern __shared__ char smc[];
    u32 smb = smem_u32(smc);
    int tid = threadIdx.x;
    int wid = tid >> 5;
    int lane = tid & 31;
    int block_m = blockIdx.y * 128;
    int block_n = blockIdx.x * 128;
    int nchunk = K >> 6;

    // ---- staging lambda: chunk ch (64 K-cols) -> stage s ----
    auto stage = [&](int s, int ch) {
        int k0 = ch << 6;
        const u16 *aH, *aL;
        int ak, astr;
        if (k0 < K0) { aH = Ah;  aL = Al;  ak = k0;      astr = K0; }
        else         { aH = A2h; aL = A2l; ak = k0 - K0; astr = K - K0; }
        for (int e = tid; e < 4096; e += 256) {
            int tile = e >> 10;
            int r = (e >> 3) & 127;
            int c = e & 7;
            const u16* g;
            int valid;
            if (tile < 2) {
                int gm = block_m + r;
                valid = gm < M;
                int gms = valid ? gm : (M - 1);   // clamp: pointer always in-bounds
                g = (tile ? aL : aH) + (size_t)gms * astr + ak + c * 8;
            } else {
                int gn = block_n + r;
                valid = gn < Nn;
                int gns = valid ? gn : (Nn - 1);
                g = (tile == 3 ? Bl : Bh) + (size_t)gns * K + k0 + c * 8;
            }
            u32 d = smb + s * STG + tile * TS + r * ROWB + c * 16;
            cp16(d, g, valid);
        }
    };

    // ---- per-lane ldmatrix offsets ----
    int wm = wid >> 2;   // 0..1
    int wn = wid & 3;    // 0..3
    int lrow = lane & 7;
    int lsel = lane >> 3;
    u32 a_off[4], b_off[2];
    #pragma unroll
    for (int mf = 0; mf < 4; mf++)
        a_off[mf] = (u32)((wm * 64 + mf * 16 + (lsel & 1) * 8 + lrow) * ROWB + (lsel >> 1) * 16);
    #pragma unroll
    for (int nb = 0; nb < 2; nb++)
        b_off[nb] = (u32)((wn * 32 + nb * 16 + (lsel >> 1) * 8 + lrow) * ROWB + (lsel & 1) * 16);

    float acc[4][4][4];
    #pragma unroll
    for (int i = 0; i < 4; i++)
        #pragma unroll
        for (int j = 0; j < 4; j++)
            #pragma unroll
            for (int q = 0; q < 4; q++) acc[i][j][q] = 0.f;

    // ---- pipeline ----
    stage(0, 0);
    asm volatile("cp.async.commit_group;");

    for (int ch = 0; ch < nchunk; ch++) {
        if (ch + 1 < nchunk) {
            stage((ch + 1) & 1, ch + 1);
            asm volatile("cp.async.commit_group;");
            asm volatile("cp.async.wait_group 1;");
        } else {
            asm volatile("cp.async.wait_group 0;");
        }
        __syncthreads();

        int s = ch & 1;
        u32 bAH = smb + s * STG;
        u32 bAL = bAH + TS;
        u32 bBH = bAH + 2 * TS;
        u32 bBL = bAH + 3 * TS;

        #pragma unroll
        for (int ks = 0; ks < 4; ks++) {
            u32 kb = (u32)(ks * 32);
            u32 ah[4][4], al[4][4], bh[4][2], bl[4][2];
            #pragma unroll
            for (int mf = 0; mf < 4; mf++) {
                ldsm_x4(ah[mf][0], ah[mf][1], ah[mf][2], ah[mf][3], bAH + a_off[mf] + kb);
                ldsm_x4(al[mf][0], al[mf][1], al[mf][2], al[mf][3], bAL + a_off[mf] + kb);
            }
            #pragma unroll
            for (int nb = 0; nb < 2; nb++) {
                u32 r0, r1, r2, r3;
                ldsm_x4(r0, r1, r2, r3, bBH + b_off[nb] + kb);
                bh[2 * nb][0] = r0; bh[2 * nb][1] = r1;
                bh[2 * nb + 1][0] = r2; bh[2 * nb + 1][1] = r3;
                ldsm_x4(r0, r1, r2, r3, bBL + b_off[nb] + kb);
                bl[2 * nb][0] = r0; bl[2 * nb][1] = r1;
                bl[2 * nb + 1][0] = r2; bl[2 * nb + 1][1] = r3;
            }
            #pragma unroll
            for (int mf = 0; mf < 4; mf++) {
                #pragma unroll
                for (int nf = 0; nf < 4; nf++) {
                    mma16816(acc[mf][nf], ah[mf][0], ah[mf][1], ah[mf][2], ah[mf][3],
                             bh[nf][0], bh[nf][1]);
                    mma16816(acc[mf][nf], ah[mf][0], ah[mf][1], ah[mf][2], ah[mf][3],
                             bl[nf][0], bl[nf][1]);
                    mma16816(acc[mf][nf], al[mf][0], al[mf][1], al[mf][2], al[mf][3],
                             bh[nf][0], bh[nf][1]);
                }
            }
        }
        __syncthreads();
    }

    // ---- epilogue: bias + lrelu + addin, split to hi/lo planes ----
    int gr = lane >> 2;
    int gc = 2 * (lane & 3);
    #pragma unroll
    for (int mf = 0; mf < 4; mf++) {
        #pragma unroll
        for (int half = 0; half < 2; half++) {
            int gm = block_m + wm * 64 + mf * 16 + gr + half * 8;
            if (gm >= M) continue;
            #pragma unroll
            for (int nf = 0; nf < 4; nf++) {
                int gn = block_n + wn * 32 + nf * 8 + gc;
                if (gn >= Nn) continue;   // Nn even, gn even -> gn+1 < Nn too
                float a0 = acc[mf][nf][half * 2 + 0] + bias[gn];
                float a1 = acc[mf][nf][half * 2 + 1] + bias[gn + 1];
                if (do_lrelu) {
                    a0 = (a0 >= 0.f) ? a0 : 0.1f * a0;
                    a1 = (a1 >= 0.f) ? a1 : 0.1f * a1;
                }
                if (addh) {
                    size_t ai = (size_t)gm * Nn + gn;
                    u32 avh = *(const u32*)(addh + ai);
                    u32 avl = *(const u32*)(addl + ai);
                    a0 += bflo(avh) + bflo(avl);
                    a1 += bfhi(avh) + bfhi(avl);
                }
                u16 h0, l0, h1, l1;
                splitf(a0, h0, l0);
                splitf(a1, h1, l1);
                size_t ci = (size_t)gm * Cs + gn;
                *(u32*)(Ch + ci) = h0 | ((u32)h1 << 16);
                *(u32*)(Cl + ci) = l0 | ((u32)l1 << 16);
            }
        }
    }
}

// ---------------------------------------------------------------------------
// Host driver
// ---------------------------------------------------------------------------
static inline dim3 pg_grid(int M, int Nn) {
    return dim3((Nn + 127) / 128, (M + 127) / 128);
}

extern "C" void kernel_launch(void* const* d_in, const int* in_sizes, int n_in,
                              void* d_out, int out_size) {
    const int*   node_ids = (const int*)  d_in[0];
    const float* content  = (const float*)d_in[1];
    const int*   src      = (const int*)  d_in[2];
    const int*   dst      = (const int*)  d_in[3];
    const float* emb      = (const float*)d_in[4];
    const float* W_exp    = (const float*)d_in[5];
    const float* b_exp    = (const float*)d_in[6];
    const float* W_p1     = (const float*)d_in[7];
    const float* b_p1     = (const float*)d_in[8];
    const float* W_p2     = (const float*)d_in[9];
    const float* b_p2     = (const float*)d_in[10];
    const float* W_conv   = (const float*)d_in[11];
    const float* b_conv   = (const float*)d_in[12];
    const float* Wo1      = (const float*)d_in[13];
    const float* bo1      = (const float*)d_in[14];
    const float* Wo2      = (const float*)d_in[15];
    const float* bo2      = (const float*)d_in[16];
    float* out = (float*)d_out;

    const int N = in_sizes[0];
    const int E = in_sizes[2];

    u16 *conth, *contl, *ch_, *cl_, *eh_, *el_, *hh_, *hl_, *th_, *tl_, *gh_, *gl_, *wh_, *wl_;
    int *p_deg, *p_off, *p_cur, *p_csr;
    cudaGetSymbolAddress((void**)&conth, g_cont_h);  cudaGetSymbolAddress((void**)&contl, g_cont_l);
    cudaGetSymbolAddress((void**)&ch_,   g_c_h);     cudaGetSymbolAddress((void**)&cl_,   g_c_l);
    cudaGetSymbolAddress((void**)&eh_,   g_e_h);     cudaGetSymbolAddress((void**)&el_,   g_e_l);
    cudaGetSymbolAddress((void**)&hh_,   g_h_h);     cudaGetSymbolAddress((void**)&hl_,   g_h_l);
    cudaGetSymbolAddress((void**)&th_,   g_t_h);     cudaGetSymbolAddress((void**)&tl_,   g_t_l);
    cudaGetSymbolAddress((void**)&gh_,   g_g_h);     cudaGetSymbolAddress((void**)&gl_,   g_g_l);
    cudaGetSymbolAddress((void**)&wh_,   g_w_h);     cudaGetSymbolAddress((void**)&wl_,   g_w_l);
    cudaGetSymbolAddress((void**)&p_deg, g_deg);     cudaGetSymbolAddress((void**)&p_off, g_off);
    cudaGetSymbolAddress((void**)&p_cur, g_cur);     cudaGetSymbolAddress((void**)&p_csr, g_csr);

    cudaFuncSetAttribute(pgemm, cudaFuncAttributeMaxDynamicSharedMemorySize, GSM);

    // ---- CSR build ----
    zero_int_kernel<<<(N + 255) / 256, 256>>>(p_deg, N);
    deg_kernel<<<(E + 255) / 256, 256>>>(dst, p_deg, E);
    scan_kernel<<<1, 1024>>>(p_deg, p_off, p_cur, N);
    fill_kernel<<<(E + 255) / 256, 256>>>(src, dst, p_cur, p_csr, E);

    // ---- split inputs to planes ----
    {
        int n1 = N * NCP;
        split_kernel<<<(n1 + 255) / 256, 256>>>(content, N, NC, NCP, conth, contl, nullptr);
        int n2 = N * ED;
        split_kernel<<<(n2 + 255) / 256, 256>>>(emb, N, ED, ED, eh_, el_, node_ids);
        split_kernel<<<(300 * NCP + 255) / 256, 256>>>(W_p1, 300, NC, NCP, wh_ + WP1, wl_ + WP1, nullptr);
        split_kernel<<<(256 * NCP + 255) / 256, 256>>>(W_p2, 256, NC, NCP, wh_ + WP2, wl_ + WP2, nullptr);
        split_kernel<<<(256 * 64 + 255) / 256, 256>>>(W_exp, 256, 64, 64, wh_ + WEXP, wl_ + WEXP, nullptr);
        split_kernel<<<(768 * 512 + 255) / 256, 256>>>(W_conv, 768, 512, 512, wh_ + WCONV, wl_ + WCONV, nullptr);
        split_kernel<<<(512 * 256 + 255) / 256, 256>>>(Wo1, 512, 256, 256, wh_ + WO1, wl_ + WO1, nullptr);
        split_kernel<<<(512 * 256 + 255) / 256, 256>>>(Wo2, 512, 256, 256, wh_ + WO2, wl_ + WO2, nullptr);
    }

    // ---- initial node representation ----
    // c = lrelu(content @ W_p1^T + b_p1)   [N,300] (Cs=320)
    pgemm<<<pg_grid(N, NC), 256, GSM>>>(conth, contl, conth, contl, NCP,
                                        wh_ + WP1, wl_ + WP1, b_p1,
                                        nullptr, nullptr,
                                        ch_, cl_, NCP, N, NC, NCP, 1);
    // t = lrelu(c @ W_p2^T + b_p2)         [N,256]
    pgemm<<<pg_grid(N, FD), 256, GSM>>>(ch_, cl_, ch_, cl_, NCP,
                                        wh_ + WP2, wl_ + WP2, b_p2,
                                        nullptr, nullptr,
                                        th_, tl_, FD, N, FD, NCP, 1);
    // h = lrelu(emb[ids] @ W_exp^T + b_exp) + t
    pgemm<<<pg_grid(N, FD), 256, GSM>>>(eh_, el_, eh_, el_, ED,
                                        wh_ + WEXP, wl_ + WEXP, b_exp,
                                        th_, tl_,
                                        hh_, hl_, FD, N, FD, ED, 1);

    const int warp_blocks = (N * 32 + 255) / 256;

    // ---- 3 SAGE layers ----
    for (int i = 0; i < 3; i++) {
        agg_pl<<<warp_blocks, 256>>>(hh_, hl_, p_off, p_csr, gh_, gl_, N);
        // t = (lrelu?)( [h, h_agg] @ W_conv[i]^T + b_conv[i] )
        pgemm<<<pg_grid(N, FD), 256, GSM>>>(hh_, hl_, gh_, gl_, FD,
                                            wh_ + WCONV + (size_t)i * FD * 2 * FD,
                                            wl_ + WCONV + (size_t)i * FD * 2 * FD,
                                            b_conv + (size_t)i * FD,
                                            nullptr, nullptr,
                                            th_, tl_, FD, N, FD, 2 * FD, (i < 2) ? 1 : 0);
        if (i < 2) {
            norm_pl<<<warp_blocks, 256>>>(th_, tl_, th_, tl_, nullptr, N);
            pgemm<<<pg_grid(N, FD), 256, GSM>>>(th_, tl_, th_, tl_, FD,
                                                wh_ + WO1 + (size_t)i * FD * FD,
                                                wl_ + WO1 + (size_t)i * FD * FD,
                                                bo1 + (size_t)i * FD,
                                                nullptr, nullptr,
                                                gh_, gl_, FD, N, FD, FD, 1);
            pgemm<<<pg_grid(N, FD), 256, GSM>>>(gh_, gl_, gh_, gl_, FD,
                                                wh_ + WO2 + (size_t)i * FD * FD,
                                                wl_ + WO2 + (size_t)i * FD * FD,
                                                bo2 + (size_t)i * FD,
                                                nullptr, nullptr,
                                                hh_, hl_, FD, N, FD, FD, 0);
        } else {
            norm_pl<<<warp_blocks, 256>>>(th_, tl_, nullptr, nullptr, out, N);
        }
    }
}

// round 15
// speedup vs baseline: 1.8858x; 1.8858x over previous
#include <cuda_runtime.h>
#include <cuda_bf16.h>
#include <stdint.h>
#include <math.h>

// ---------------------------------------------------------------------------
// Problem constants
// ---------------------------------------------------------------------------
#define NNODES 50000
#define NEDGES 1000000
#define FD     256
#define NC     300
#define NCP    320   // NC padded to multiple of 32
#define ED     64

typedef unsigned short u16;
typedef unsigned int   u32;

// ---------------------------------------------------------------------------
// Scratch (device globals — no allocation allowed)
// All activations/weights stored as split bf16 "planes": hi plane + lo plane,
// value = float(hi) + float(lo)  (≈ fp32 with 16-bit mantissa, err ~2^-17).
// ---------------------------------------------------------------------------
__device__ u16 g_cont_h[NNODES * NCP], g_cont_l[NNODES * NCP];
__device__ u16 g_c_h[NNODES * NCP],    g_c_l[NNODES * NCP];
__device__ u16 g_e_h[NNODES * ED],     g_e_l[NNODES * ED];
__device__ u16 g_h_h[NNODES * FD],     g_h_l[NNODES * FD];
__device__ u16 g_t_h[NNODES * FD],     g_t_l[NNODES * FD];
__device__ u16 g_g_h[NNODES * FD],     g_g_l[NNODES * FD];

// weight-plane offsets (u16 elements)
#define WP1   0
#define WP2   96000              // + 300*320
#define WEXP  177920             // + 256*320
#define WCONV 194304             // + 256*64
#define WO1   587520             // + 3*256*512
#define WO2   718592             // + 2*256*256
#define WTOT  849664             // + 2*256*256
__device__ u16 g_w_h[WTOT], g_w_l[WTOT];

__device__ int g_deg[NNODES];
__device__ int g_off[NNODES + 1];
__device__ int g_cur[NNODES];
__device__ int g_csr[NEDGES];

// ---------------------------------------------------------------------------
// Helpers
// ---------------------------------------------------------------------------
__device__ __forceinline__ u32 smem_u32(const void* p) {
    u32 a;
    asm("{ .reg .u64 t; cvta.to.shared.u64 t, %1; cvt.u32.u64 %0, t; }" : "=r"(a) : "l"(p));
    return a;
}
__device__ __forceinline__ void splitf(float x, u16& h, u16& l) {
    __nv_bfloat16 hb = __float2bfloat16(x);
    float hf = __bfloat162float(hb);
    __nv_bfloat16 lb = __float2bfloat16(x - hf);
    h = __bfloat16_as_ushort(hb);
    l = __bfloat16_as_ushort(lb);
}
// bf16 bits -> fp32 (low / high half of a packed u32) — pure bit ops
__device__ __forceinline__ float bflo(u32 u) { return __uint_as_float(u << 16); }
__device__ __forceinline__ float bfhi(u32 u) { return __uint_as_float(u & 0xFFFF0000u); }

__device__ __forceinline__ void ldsm_x4(u32& r0, u32& r1, u32& r2, u32& r3, u32 addr) {
    asm volatile("ldmatrix.sync.aligned.m8n8.x4.shared.b16 {%0,%1,%2,%3}, [%4];"
                 : "=r"(r0), "=r"(r1), "=r"(r2), "=r"(r3) : "r"(addr));
}
__device__ __forceinline__ void mma16816(float* c, u32 a0, u32 a1, u32 a2, u32 a3,
                                         u32 b0, u32 b1) {
    asm volatile("mma.sync.aligned.m16n8k16.row.col.f32.bf16.bf16.f32 "
                 "{%0,%1,%2,%3}, {%4,%5,%6,%7}, {%8,%9}, {%0,%1,%2,%3};"
                 : "+f"(c[0]), "+f"(c[1]), "+f"(c[2]), "+f"(c[3])
                 : "r"(a0), "r"(a1), "r"(a2), "r"(a3), "r"(b0), "r"(b1));
}
// cp.async with zfill mask: pointer is ALWAYS in-bounds (caller clamps row),
// src-size=0 only zero-fills.
__device__ __forceinline__ void cp16(u32 dst, const void* src, int valid) {
    asm volatile("cp.async.cg.shared.global [%0], [%1], 16, %2;"
                 :: "r"(dst), "l"(src), "r"(valid ? 16 : 0));
}

// ---------------------------------------------------------------------------
// Prep: split fp32 matrix (rows x sc) into hi/lo planes (rows x dc, zero-pad),
// optional row gather.
// ---------------------------------------------------------------------------
__global__ void split_kernel(const float* __restrict__ src, int rows, int sc, int dc,
                             u16* __restrict__ dh, u16* __restrict__ dl,
                             const int* __restrict__ gather) {
    int i = blockIdx.x * blockDim.x + threadIdx.x;
    if (i >= rows * dc) return;
    int r = i / dc, c = i - r * dc;
    float v = 0.f;
    if (c < sc) {
        int rr = gather ? gather[r] : r;
        v = src[(size_t)rr * sc + c];
    }
    u16 h, l;
    splitf(v, h, l);
    dh[i] = h;
    dl[i] = l;
}

// ---------------------------------------------------------------------------
// CSR build kernels
// ---------------------------------------------------------------------------
__global__ void zero_int_kernel(int* p, int n) {
    int i = blockIdx.x * blockDim.x + threadIdx.x;
    if (i < n) p[i] = 0;
}
__global__ void deg_kernel(const int* __restrict__ dst, int* __restrict__ deg, int e) {
    int i = blockIdx.x * blockDim.x + threadIdx.x;
    if (i < e) atomicAdd(&deg[dst[i]], 1);
}
__global__ void scan_kernel(const int* __restrict__ deg, int* __restrict__ off,
                            int* __restrict__ cur, int n) {
    __shared__ int sh[1024];
    __shared__ int carry;
    int tid = threadIdx.x;
    if (tid == 0) carry = 0;
    __syncthreads();
    for (int base = 0; base < n; base += 1024) {
        int i = base + tid;
        int v = (i < n) ? deg[i] : 0;
        sh[tid] = v;
        __syncthreads();
        #pragma unroll
        for (int s = 1; s < 1024; s <<= 1) {
            int t = (tid >= s) ? sh[tid - s] : 0;
            __syncthreads();
            sh[tid] += t;
            __syncthreads();
        }
        int excl = sh[tid] - v + carry;
        if (i < n) { off[i] = excl; cur[i] = excl; }
        __syncthreads();
        if (tid == 0) carry += sh[1023];
        __syncthreads();
    }
    if (tid == 0) off[n] = carry;
}
__global__ void fill_kernel(const int* __restrict__ src, const int* __restrict__ dst,
                            int* __restrict__ cur, int* __restrict__ csr, int e) {
    int i = blockIdx.x * blockDim.x + threadIdx.x;
    if (i < e) {
        int d = dst[i];
        int p = atomicAdd(&cur[d], 1);
        csr[p] = src[i];
    }
}

// ---------------------------------------------------------------------------
// Aggregation on planes: o[n,:] = (sum_{s in CSR[n]} h[s,:]) / max(deg,1)
// Warp per node, lane owns 8 columns. 4-neighbor unroll for MLP.
// ---------------------------------------------------------------------------
#define ACC8(hv, lv)                                                   \
    { acc[0] += bflo(hv.x) + bflo(lv.x); acc[1] += bfhi(hv.x) + bfhi(lv.x); \
      acc[2] += bflo(hv.y) + bflo(lv.y); acc[3] += bfhi(hv.y) + bfhi(lv.y); \
      acc[4] += bflo(hv.z) + bflo(lv.z); acc[5] += bfhi(hv.z) + bfhi(lv.z); \
      acc[6] += bflo(hv.w) + bflo(lv.w); acc[7] += bfhi(hv.w) + bfhi(lv.w); }

__global__ void agg_pl(const u16* __restrict__ hh, const u16* __restrict__ hl,
                       const int* __restrict__ off, const int* __restrict__ csr,
                       u16* __restrict__ oh, u16* __restrict__ ol, int n) {
    int w = (blockIdx.x * blockDim.x + threadIdx.x) >> 5;
    int lane = threadIdx.x & 31;
    if (w >= n) return;
    int beg = off[w], end = off[w + 1];
    size_t lo8 = (size_t)lane * 8;

    float acc[8];
    #pragma unroll
    for (int i = 0; i < 8; i++) acc[i] = 0.f;

    int j = beg;
    for (; j + 3 < end; j += 4) {
        int s0 = csr[j], s1 = csr[j + 1], s2 = csr[j + 2], s3 = csr[j + 3];
        uint4 h0 = *(const uint4*)(hh + (size_t)s0 * FD + lo8);
        uint4 l0 = *(const uint4*)(hl + (size_t)s0 * FD + lo8);
        uint4 h1 = *(const uint4*)(hh + (size_t)s1 * FD + lo8);
        uint4 l1 = *(const uint4*)(hl + (size_t)s1 * FD + lo8);
        uint4 h2 = *(const uint4*)(hh + (size_t)s2 * FD + lo8);
        uint4 l2 = *(const uint4*)(hl + (size_t)s2 * FD + lo8);
        uint4 h3 = *(const uint4*)(hh + (size_t)s3 * FD + lo8);
        uint4 l3 = *(const uint4*)(hl + (size_t)s3 * FD + lo8);
        ACC8(h0, l0);
        ACC8(h1, l1);
        ACC8(h2, l2);
        ACC8(h3, l3);
    }
    for (; j < end; j++) {
        int s0 = csr[j];
        uint4 h0 = *(const uint4*)(hh + (size_t)s0 * FD + lo8);
        uint4 l0 = *(const uint4*)(hl + (size_t)s0 * FD + lo8);
        ACC8(h0, l0);
    }
    int d = end - beg;
    float inv = 1.f / (float)(d > 0 ? d : 1);

    u16 sh[8], sl[8];
    #pragma unroll
    for (int i = 0; i < 8; i++) splitf(acc[i] * inv, sh[i], sl[i]);
    uint4 vh, vl;
    vh.x = sh[0] | ((u32)sh[1] << 16); vl.x = sl[0] | ((u32)sl[1] << 16);
    vh.y = sh[2] | ((u32)sh[3] << 16); vl.y = sl[2] | ((u32)sl[3] << 16);
    vh.z = sh[4] | ((u32)sh[5] << 16); vl.z = sl[4] | ((u32)sl[5] << 16);
    vh.w = sh[6] | ((u32)sh[7] << 16); vl.w = sl[6] | ((u32)sl[7] << 16);
    *(uint4*)(oh + (size_t)w * FD + lo8) = vh;
    *(uint4*)(ol + (size_t)w * FD + lo8) = vl;
}

// ---------------------------------------------------------------------------
// Row L2 normalize on planes. If of != null, write fp32 there instead.
// ---------------------------------------------------------------------------
__global__ void norm_pl(const u16* __restrict__ th, const u16* __restrict__ tl,
                        u16* __restrict__ oh, u16* __restrict__ ol,
                        float* __restrict__ of, int n) {
    int w = (blockIdx.x * blockDim.x + threadIdx.x) >> 5;
    int lane = threadIdx.x & 31;
    if (w >= n) return;
    size_t lo8 = (size_t)lane * 8;
    uint4 hv = *(const uint4*)(th + (size_t)w * FD + lo8);
    uint4 lv = *(const uint4*)(tl + (size_t)w * FD + lo8);
    float x[8];
    x[0] = bflo(hv.x) + bflo(lv.x); x[1] = bfhi(hv.x) + bfhi(lv.x);
    x[2] = bflo(hv.y) + bflo(lv.y); x[3] = bfhi(hv.y) + bfhi(lv.y);
    x[4] = bflo(hv.z) + bflo(lv.z); x[5] = bfhi(hv.z) + bfhi(lv.z);
    x[6] = bflo(hv.w) + bflo(lv.w); x[7] = bfhi(hv.w) + bfhi(lv.w);
    float s = 0.f;
    #pragma unroll
    for (int i = 0; i < 8; i++) s += x[i] * x[i];
    #pragma unroll
    for (int o = 16; o; o >>= 1) s += __shfl_xor_sync(0xFFFFFFFFu, s, o);
    float inv = 1.f / fmaxf(sqrtf(s), 1e-6f);
    #pragma unroll
    for (int i = 0; i < 8; i++) x[i] *= inv;

    if (of) {
        float4 a = make_float4(x[0], x[1], x[2], x[3]);
        float4 b = make_float4(x[4], x[5], x[6], x[7]);
        *(float4*)(of + (size_t)w * FD + lo8)     = a;
        *(float4*)(of + (size_t)w * FD + lo8 + 4) = b;
    } else {
        u16 sh[8], sl[8];
        #pragma unroll
        for (int i = 0; i < 8; i++) splitf(x[i], sh[i], sl[i]);
        uint4 vh, vl;
        vh.x = sh[0] | ((u32)sh[1] << 16); vl.x = sl[0] | ((u32)sl[1] << 16);
        vh.y = sh[2] | ((u32)sh[3] << 16); vl.y = sl[2] | ((u32)sl[3] << 16);
        vh.z = sh[4] | ((u32)sh[5] << 16); vl.z = sl[4] | ((u32)sl[5] << 16);
        vh.w = sh[6] | ((u32)sh[7] << 16); vl.w = sl[6] | ((u32)sl[7] << 16);
        *(uint4*)(oh + (size_t)w * FD + lo8) = vh;
        *(uint4*)(ol + (size_t)w * FD + lo8) = vl;
    }
}

// ---------------------------------------------------------------------------
// Plane GEMM (split-bf16, 3-pass: AhBh + AhBl + AlBh, fp32 accum):
//   C[m,n] = act( sum_k A[m,k]*B[n,k] + bias[n] ) (+ addin) -> hi/lo planes
// A concat: k < K0 from (Ah,Al) stride K0; k >= K0 from (A2h,A2l) stride K-K0.
// B planes stride K. Tile 128x128, K-chunk 32, 2-stage cp.async pipeline.
// SMEM tiles: 128 rows x 32 bf16, row stride 80B (conflict-free ldmatrix).
// GSM=81920 -> 2 CTAs/SM (163840 <= 227KB); __launch_bounds__(256,2) pins it.
// OOB rows: pointer clamped in-bounds, cp.async zfill writes zeros.
// ---------------------------------------------------------------------------
#define TS   10240            // one tile: 128*80 bytes
#define STG  (4 * TS)         // Ah,Al,Bh,Bl per stage
#define GSM  (2 * STG)        // 81920 bytes dynamic smem
#define ROWB 80

__global__ void __launch_bounds__(256, 2)
pgemm(const u16* __restrict__ Ah, const u16* __restrict__ Al,
      const u16* __restrict__ A2h, const u16* __restrict__ A2l, int K0,
      const u16* __restrict__ Bh, const u16* __restrict__ Bl,
      const float* __restrict__ bias,
      const u16* __restrict__ addh, const u16* __restrict__ addl,
      u16* __restrict__ Ch, u16* __restrict__ Cl, int Cs,
      int M, int Nn, int K, int do_lrelu) {
    extern __shared__ char smc[];
    u32 smb = smem_u32(smc);
    int tid = threadIdx.x;
    int wid = tid >> 5;
    int lane = tid & 31;
    int block_m = blockIdx.y * 128;
    int block_n = blockIdx.x * 128;
    int nchunk = K >> 5;

    // ---- staging lambda: chunk ch -> stage s ----
    auto stage = [&](int s, int ch) {
        int k0 = ch << 5;
        const u16 *aH, *aL;
        int ak, astr;
        if (k0 < K0) { aH = Ah;  aL = Al;  ak = k0;      astr = K0; }
        else         { aH = A2h; aL = A2l; ak = k0 - K0; astr = K - K0; }
        for (int e = tid; e < 2048; e += 256) {
            int tile = e >> 9;
            int r = (e >> 2) & 127;
            int c = e & 3;
            const u16* g;
            int valid;
            if (tile < 2) {
                int gm = block_m + r;
                valid = gm < M;
                int gms = valid ? gm : (M - 1);   // clamp: pointer always in-bounds
                g = (tile ? aL : aH) + (size_t)gms * astr + ak + c * 8;
            } else {
                int gn = block_n + r;
                valid = gn < Nn;
                int gns = valid ? gn : (Nn - 1);
                g = (tile == 3 ? Bl : Bh) + (size_t)gns * K + k0 + c * 8;
            }
            u32 d = smb + s * STG + tile * TS + r * ROWB + c * 16;
            cp16(d, g, valid);
        }
    };

    // ---- per-lane ldmatrix offsets ----
    int wm = wid >> 2;   // 0..1
    int wn = wid & 3;    // 0..3
    int lrow = lane & 7;
    int lsel = lane >> 3;
    u32 a_off[4], b_off[2];
    #pragma unroll
    for (int mf = 0; mf < 4; mf++)
        a_off[mf] = (u32)((wm * 64 + mf * 16 + (lsel & 1) * 8 + lrow) * ROWB + (lsel >> 1) * 16);
    #pragma unroll
    for (int nb = 0; nb < 2; nb++)
        b_off[nb] = (u32)((wn * 32 + nb * 16 + (lsel >> 1) * 8 + lrow) * ROWB + (lsel & 1) * 16);

    float acc[4][4][4];
    #pragma unroll
    for (int i = 0; i < 4; i++)
        #pragma unroll
        for (int j = 0; j < 4; j++)
            #pragma unroll
            for (int q = 0; q < 4; q++) acc[i][j][q] = 0.f;

    // ---- pipeline ----
    stage(0, 0);
    asm volatile("cp.async.commit_group;");

    for (int ch = 0; ch < nchunk; ch++) {
        if (ch + 1 < nchunk) {
            stage((ch + 1) & 1, ch + 1);
            asm volatile("cp.async.commit_group;");
            asm volatile("cp.async.wait_group 1;");
        } else {
            asm volatile("cp.async.wait_group 0;");
        }
        __syncthreads();

        int s = ch & 1;
        u32 bAH = smb + s * STG;
        u32 bAL = bAH + TS;
        u32 bBH = bAH + 2 * TS;
        u32 bBL = bAH + 3 * TS;

        #pragma unroll
        for (int ks = 0; ks < 2; ks++) {
            u32 kb = (u32)(ks * 32);
            u32 ah[4][4], al[4][4], bh[4][2], bl[4][2];
            #pragma unroll
            for (int mf = 0; mf < 4; mf++) {
                ldsm_x4(ah[mf][0], ah[mf][1], ah[mf][2], ah[mf][3], bAH + a_off[mf] + kb);
                ldsm_x4(al[mf][0], al[mf][1], al[mf][2], al[mf][3], bAL + a_off[mf] + kb);
            }
            #pragma unroll
            for (int nb = 0; nb < 2; nb++) {
                u32 r0, r1, r2, r3;
                ldsm_x4(r0, r1, r2, r3, bBH + b_off[nb] + kb);
                bh[2 * nb][0] = r0; bh[2 * nb][1] = r1;
                bh[2 * nb + 1][0] = r2; bh[2 * nb + 1][1] = r3;
                ldsm_x4(r0, r1, r2, r3, bBL + b_off[nb] + kb);
                bl[2 * nb][0] = r0; bl[2 * nb][1] = r1;
                bl[2 * nb + 1][0] = r2; bl[2 * nb + 1][1] = r3;
            }
            #pragma unroll
            for (int mf = 0; mf < 4; mf++) {
                #pragma unroll
                for (int nf = 0; nf < 4; nf++) {
                    mma16816(acc[mf][nf], ah[mf][0], ah[mf][1], ah[mf][2], ah[mf][3],
                             bh[nf][0], bh[nf][1]);
                    mma16816(acc[mf][nf], ah[mf][0], ah[mf][1], ah[mf][2], ah[mf][3],
                             bl[nf][0], bl[nf][1]);
                    mma16816(acc[mf][nf], al[mf][0], al[mf][1], al[mf][2], al[mf][3],
                             bh[nf][0], bh[nf][1]);
                }
            }
        }
        __syncthreads();
    }

    // ---- epilogue: bias + lrelu + addin, split to hi/lo planes ----
    int gr = lane >> 2;
    int gc = 2 * (lane & 3);
    #pragma unroll
    for (int mf = 0; mf < 4; mf++) {
        #pragma unroll
        for (int half = 0; half < 2; half++) {
            int gm = block_m + wm * 64 + mf * 16 + gr + half * 8;
            if (gm >= M) continue;
            #pragma unroll
            for (int nf = 0; nf < 4; nf++) {
                int gn = block_n + wn * 32 + nf * 8 + gc;
                if (gn >= Nn) continue;   // Nn even, gn even -> gn+1 < Nn too
                float a0 = acc[mf][nf][half * 2 + 0] + bias[gn];
                float a1 = acc[mf][nf][half * 2 + 1] + bias[gn + 1];
                if (do_lrelu) {
                    a0 = (a0 >= 0.f) ? a0 : 0.1f * a0;
                    a1 = (a1 >= 0.f) ? a1 : 0.1f * a1;
                }
                if (addh) {
                    size_t ai = (size_t)gm * Nn + gn;
                    u32 avh = *(const u32*)(addh + ai);
                    u32 avl = *(const u32*)(addl + ai);
                    a0 += bflo(avh) + bflo(avl);
                    a1 += bfhi(avh) + bfhi(avl);
                }
                u16 h0, l0, h1, l1;
                splitf(a0, h0, l0);
                splitf(a1, h1, l1);
                size_t ci = (size_t)gm * Cs + gn;
                *(u32*)(Ch + ci) = h0 | ((u32)h1 << 16);
                *(u32*)(Cl + ci) = l0 | ((u32)l1 << 16);
            }
        }
    }
}

// ---------------------------------------------------------------------------
// Host driver
// ---------------------------------------------------------------------------
static inline dim3 pg_grid(int M, int Nn) {
    return dim3((Nn + 127) / 128, (M + 127) / 128);
}

extern "C" void kernel_launch(void* const* d_in, const int* in_sizes, int n_in,
                              void* d_out, int out_size) {
    const int*   node_ids = (const int*)  d_in[0];
    const float* content  = (const float*)d_in[1];
    const int*   src      = (const int*)  d_in[2];
    const int*   dst      = (const int*)  d_in[3];
    const float* emb      = (const float*)d_in[4];
    const float* W_exp    = (const float*)d_in[5];
    const float* b_exp    = (const float*)d_in[6];
    const float* W_p1     = (const float*)d_in[7];
    const float* b_p1     = (const float*)d_in[8];
    const float* W_p2     = (const float*)d_in[9];
    const float* b_p2     = (const float*)d_in[10];
    const float* W_conv   = (const float*)d_in[11];
    const float* b_conv   = (const float*)d_in[12];
    const float* Wo1      = (const float*)d_in[13];
    const float* bo1      = (const float*)d_in[14];
    const float* Wo2      = (const float*)d_in[15];
    const float* bo2      = (const float*)d_in[16];
    float* out = (float*)d_out;

    const int N = in_sizes[0];
    const int E = in_sizes[2];

    u16 *conth, *contl, *ch_, *cl_, *eh_, *el_, *hh_, *hl_, *th_, *tl_, *gh_, *gl_, *wh_, *wl_;
    int *p_deg, *p_off, *p_cur, *p_csr;
    cudaGetSymbolAddress((void**)&conth, g_cont_h);  cudaGetSymbolAddress((void**)&contl, g_cont_l);
    cudaGetSymbolAddress((void**)&ch_,   g_c_h);     cudaGetSymbolAddress((void**)&cl_,   g_c_l);
    cudaGetSymbolAddress((void**)&eh_,   g_e_h);     cudaGetSymbolAddress((void**)&el_,   g_e_l);
    cudaGetSymbolAddress((void**)&hh_,   g_h_h);     cudaGetSymbolAddress((void**)&hl_,   g_h_l);
    cudaGetSymbolAddress((void**)&th_,   g_t_h);     cudaGetSymbolAddress((void**)&tl_,   g_t_l);
    cudaGetSymbolAddress((void**)&gh_,   g_g_h);     cudaGetSymbolAddress((void**)&gl_,   g_g_l);
    cudaGetSymbolAddress((void**)&wh_,   g_w_h);     cudaGetSymbolAddress((void**)&wl_,   g_w_l);
    cudaGetSymbolAddress((void**)&p_deg, g_deg);     cudaGetSymbolAddress((void**)&p_off, g_off);
    cudaGetSymbolAddress((void**)&p_cur, g_cur);     cudaGetSymbolAddress((void**)&p_csr, g_csr);

    cudaFuncSetAttribute(pgemm, cudaFuncAttributeMaxDynamicSharedMemorySize, GSM);

    // ---- CSR build ----
    zero_int_kernel<<<(N + 255) / 256, 256>>>(p_deg, N);
    deg_kernel<<<(E + 255) / 256, 256>>>(dst, p_deg, E);
    scan_kernel<<<1, 1024>>>(p_deg, p_off, p_cur, N);
    fill_kernel<<<(E + 255) / 256, 256>>>(src, dst, p_cur, p_csr, E);

    // ---- split inputs to planes ----
    {
        int n1 = N * NCP;
        split_kernel<<<(n1 + 255) / 256, 256>>>(content, N, NC, NCP, conth, contl, nullptr);
        int n2 = N * ED;
        split_kernel<<<(n2 + 255) / 256, 256>>>(emb, N, ED, ED, eh_, el_, node_ids);
        split_kernel<<<(300 * NCP + 255) / 256, 256>>>(W_p1, 300, NC, NCP, wh_ + WP1, wl_ + WP1, nullptr);
        split_kernel<<<(256 * NCP + 255) / 256, 256>>>(W_p2, 256, NC, NCP, wh_ + WP2, wl_ + WP2, nullptr);
        split_kernel<<<(256 * 64 + 255) / 256, 256>>>(W_exp, 256, 64, 64, wh_ + WEXP, wl_ + WEXP, nullptr);
        split_kernel<<<(768 * 512 + 255) / 256, 256>>>(W_conv, 768, 512, 512, wh_ + WCONV, wl_ + WCONV, nullptr);
        split_kernel<<<(512 * 256 + 255) / 256, 256>>>(Wo1, 512, 256, 256, wh_ + WO1, wl_ + WO1, nullptr);
        split_kernel<<<(512 * 256 + 255) / 256, 256>>>(Wo2, 512, 256, 256, wh_ + WO2, wl_ + WO2, nullptr);
    }

    // ---- initial node representation ----
    // c = lrelu(content @ W_p1^T + b_p1)   [N,300] (Cs=320)
    pgemm<<<pg_grid(N, NC), 256, GSM>>>(conth, contl, conth, contl, NCP,
                                        wh_ + WP1, wl_ + WP1, b_p1,
                                        nullptr, nullptr,
                                        ch_, cl_, NCP, N, NC, NCP, 1);
    // t = lrelu(c @ W_p2^T + b_p2)         [N,256]
    pgemm<<<pg_grid(N, FD), 256, GSM>>>(ch_, cl_, ch_, cl_, NCP,
                                        wh_ + WP2, wl_ + WP2, b_p2,
                                        nullptr, nullptr,
                                        th_, tl_, FD, N, FD, NCP, 1);
    // h = lrelu(emb[ids] @ W_exp^T + b_exp) + t
    pgemm<<<pg_grid(N, FD), 256, GSM>>>(eh_, el_, eh_, el_, ED,
                                        wh_ + WEXP, wl_ + WEXP, b_exp,
                                        th_, tl_,
                                        hh_, hl_, FD, N, FD, ED, 1);

    const int warp_blocks = (N * 32 + 255) / 256;

    // ---- 3 SAGE layers ----
    for (int i = 0; i < 3; i++) {
        agg_pl<<<warp_blocks, 256>>>(hh_, hl_, p_off, p_csr, gh_, gl_, N);
        // t = (lrelu?)( [h, h_agg] @ W_conv[i]^T + b_conv[i] )
        pgemm<<<pg_grid(N, FD), 256, GSM>>>(hh_, hl_, gh_, gl_, FD,
                                            wh_ + WCONV + (size_t)i * FD * 2 * FD,
                                            wl_ + WCONV + (size_t)i * FD * 2 * FD,
                                            b_conv + (size_t)i * FD,
                                            nullptr, nullptr,
                                            th_, tl_, FD, N, FD, 2 * FD, (i < 2) ? 1 : 0);
        if (i < 2) {
            norm_pl<<<warp_blocks, 256>>>(th_, tl_, th_, tl_, nullptr, N);
            pgemm<<<pg_grid(N, FD), 256, GSM>>>(th_, tl_, th_, tl_, FD,
                                                wh_ + WO1 + (size_t)i * FD * FD,
                                                wl_ + WO1 + (size_t)i * FD * FD,
                                                bo1 + (size_t)i * FD,
                                                nullptr, nullptr,
                                                gh_, gl_, FD, N, FD, FD, 1);
            pgemm<<<pg_grid(N, FD), 256, GSM>>>(gh_, gl_, gh_, gl_, FD,
                                                wh_ + WO2 + (size_t)i * FD * FD,
                                                wl_ + WO2 + (size_t)i * FD * FD,
                                                bo2 + (size_t)i * FD,
                                                nullptr, nullptr,
                                                hh_, hl_, FD, N, FD, FD, 0);
        } else {
            norm_pl<<<warp_blocks, 256>>>(th_, tl_, nullptr, nullptr, out, N);
        }
    }
}

// round 16
// speedup vs baseline: 2.0507x; 1.0875x over previous
#include <cuda_runtime.h>
#include <cuda_fp16.h>
#include <stdint.h>
#include <math.h>

// ---------------------------------------------------------------------------
// Problem constants
// ---------------------------------------------------------------------------
#define NNODES 50000
#define NEDGES 1000000
#define FD     256
#define NC     300
#define NCP    320   // NC padded to multiple of 32
#define ED     64

typedef unsigned short u16;
typedef unsigned int   u32;

// ---------------------------------------------------------------------------
// Scratch (device globals — no allocation allowed)
// Activations: split fp16 planes (hi + lo), value = float(hi)+float(lo)
// (~22 mantissa bits, err ~2^-22). Weights: single fp16 plane (err 2^-12).
// ---------------------------------------------------------------------------
__device__ u16 g_cont_h[NNODES * NCP], g_cont_l[NNODES * NCP];
__device__ u16 g_c_h[NNODES * NCP],    g_c_l[NNODES * NCP];
__device__ u16 g_e_h[NNODES * ED],     g_e_l[NNODES * ED];
__device__ u16 g_h_h[NNODES * FD],     g_h_l[NNODES * FD];
__device__ u16 g_t_h[NNODES * FD],     g_t_l[NNODES * FD];
__device__ u16 g_g_h[NNODES * FD],     g_g_l[NNODES * FD];

// weight-plane offsets (u16 elements) — single fp16 plane
#define WP1   0
#define WP2   96000              // + 300*320
#define WEXP  177920             // + 256*320
#define WCONV 194304             // + 256*64
#define WO1   587520             // + 3*256*512
#define WO2   718592             // + 2*256*256
#define WTOT  849664             // + 2*256*256
__device__ u16 g_w[WTOT];

__device__ int g_deg[NNODES];
__device__ int g_off[NNODES + 1];
__device__ int g_cur[NNODES];
__device__ int g_csr[NEDGES];

// ---------------------------------------------------------------------------
// Helpers
// ---------------------------------------------------------------------------
__device__ __forceinline__ u32 smem_u32(const void* p) {
    u32 a;
    asm("{ .reg .u64 t; cvta.to.shared.u64 t, %1; cvt.u32.u64 %0, t; }" : "=r"(a) : "l"(p));
    return a;
}
// split fp32 -> fp16 hi + fp16 lo
__device__ __forceinline__ void splith(float x, u16& h, u16& l) {
    __half hb = __float2half(x);
    float hf = __half2float(hb);
    __half lb = __float2half(x - hf);
    h = __half_as_ushort(hb);
    l = __half_as_ushort(lb);
}
// packed u32 (2 fp16) -> float2
__device__ __forceinline__ float2 h22f2(u32 u) {
    __half2 hv = *reinterpret_cast<const __half2*>(&u);
    return __half22float2(hv);
}
__device__ __forceinline__ u32 packh(u16 a, u16 b) { return (u32)a | ((u32)b << 16); }

__device__ __forceinline__ void ldsm_x4(u32& r0, u32& r1, u32& r2, u32& r3, u32 addr) {
    asm volatile("ldmatrix.sync.aligned.m8n8.x4.shared.b16 {%0,%1,%2,%3}, [%4];"
                 : "=r"(r0), "=r"(r1), "=r"(r2), "=r"(r3) : "r"(addr));
}
__device__ __forceinline__ void mma16816(float* c, u32 a0, u32 a1, u32 a2, u32 a3,
                                         u32 b0, u32 b1) {
    asm volatile("mma.sync.aligned.m16n8k16.row.col.f32.f16.f16.f32 "
                 "{%0,%1,%2,%3}, {%4,%5,%6,%7}, {%8,%9}, {%0,%1,%2,%3};"
                 : "+f"(c[0]), "+f"(c[1]), "+f"(c[2]), "+f"(c[3])
                 : "r"(a0), "r"(a1), "r"(a2), "r"(a3), "r"(b0), "r"(b1));
}
// cp.async with zfill mask: pointer ALWAYS in-bounds (caller clamps row).
__device__ __forceinline__ void cp16(u32 dst, const void* src, int valid) {
    asm volatile("cp.async.cg.shared.global [%0], [%1], 16, %2;"
                 :: "r"(dst), "l"(src), "r"(valid ? 16 : 0));
}

// ---------------------------------------------------------------------------
// Prep kernels
// ---------------------------------------------------------------------------
// activations: fp32 -> fp16 hi/lo planes (zero-pad cols), optional gather
__global__ void splita_kernel(const float* __restrict__ src, int rows, int sc, int dc,
                              u16* __restrict__ dh, u16* __restrict__ dl,
                              const int* __restrict__ gather) {
    int i = blockIdx.x * blockDim.x + threadIdx.x;
    if (i >= rows * dc) return;
    int r = i / dc, c = i - r * dc;
    float v = 0.f;
    if (c < sc) {
        int rr = gather ? gather[r] : r;
        v = src[(size_t)rr * sc + c];
    }
    u16 h, l;
    splith(v, h, l);
    dh[i] = h;
    dl[i] = l;
}
// weights: fp32 -> single fp16 plane (zero-pad cols)
__global__ void splitw_kernel(const float* __restrict__ src, int rows, int sc, int dc,
                              u16* __restrict__ dw) {
    int i = blockIdx.x * blockDim.x + threadIdx.x;
    if (i >= rows * dc) return;
    int r = i / dc, c = i - r * dc;
    float v = (c < sc) ? src[(size_t)r * sc + c] : 0.f;
    dw[i] = __half_as_ushort(__float2half(v));
}

// ---------------------------------------------------------------------------
// CSR build kernels
// ---------------------------------------------------------------------------
__global__ void zero_int_kernel(int* p, int n) {
    int i = blockIdx.x * blockDim.x + threadIdx.x;
    if (i < n) p[i] = 0;
}
__global__ void deg_kernel(const int* __restrict__ dst, int* __restrict__ deg, int e) {
    int i = blockIdx.x * blockDim.x + threadIdx.x;
    if (i < e) atomicAdd(&deg[dst[i]], 1);
}
__global__ void scan_kernel(const int* __restrict__ deg, int* __restrict__ off,
                            int* __restrict__ cur, int n) {
    __shared__ int sh[1024];
    __shared__ int carry;
    int tid = threadIdx.x;
    if (tid == 0) carry = 0;
    __syncthreads();
    for (int base = 0; base < n; base += 1024) {
        int i = base + tid;
        int v = (i < n) ? deg[i] : 0;
        sh[tid] = v;
        __syncthreads();
        #pragma unroll
        for (int s = 1; s < 1024; s <<= 1) {
            int t = (tid >= s) ? sh[tid - s] : 0;
            __syncthreads();
            sh[tid] += t;
            __syncthreads();
        }
        int excl = sh[tid] - v + carry;
        if (i < n) { off[i] = excl; cur[i] = excl; }
        __syncthreads();
        if (tid == 0) carry += sh[1023];
        __syncthreads();
    }
    if (tid == 0) off[n] = carry;
}
__global__ void fill_kernel(const int* __restrict__ src, const int* __restrict__ dst,
                            int* __restrict__ cur, int* __restrict__ csr, int e) {
    int i = blockIdx.x * blockDim.x + threadIdx.x;
    if (i < e) {
        int d = dst[i];
        int p = atomicAdd(&cur[d], 1);
        csr[p] = src[i];
    }
}

// ---------------------------------------------------------------------------
// Aggregation on planes: o[n,:] = (sum_{s in CSR[n]} h[s,:]) / max(deg,1)
// Warp per node, lane owns 8 columns. 4-neighbor unroll for MLP.
// ---------------------------------------------------------------------------
#define ACC8(hv, lv)                                                          \
    { float2 a_ = h22f2(hv.x), b_ = h22f2(lv.x);                              \
      acc[0] += a_.x + b_.x; acc[1] += a_.y + b_.y;                           \
      a_ = h22f2(hv.y); b_ = h22f2(lv.y);                                     \
      acc[2] += a_.x + b_.x; acc[3] += a_.y + b_.y;                           \
      a_ = h22f2(hv.z); b_ = h22f2(lv.z);                                     \
      acc[4] += a_.x + b_.x; acc[5] += a_.y + b_.y;                           \
      a_ = h22f2(hv.w); b_ = h22f2(lv.w);                                     \
      acc[6] += a_.x + b_.x; acc[7] += a_.y + b_.y; }

__global__ void agg_pl(const u16* __restrict__ hh, const u16* __restrict__ hl,
                       const int* __restrict__ off, const int* __restrict__ csr,
                       u16* __restrict__ oh, u16* __restrict__ ol, int n) {
    int w = (blockIdx.x * blockDim.x + threadIdx.x) >> 5;
    int lane = threadIdx.x & 31;
    if (w >= n) return;
    int beg = off[w], end = off[w + 1];
    size_t lo8 = (size_t)lane * 8;

    float acc[8];
    #pragma unroll
    for (int i = 0; i < 8; i++) acc[i] = 0.f;

    int j = beg;
    for (; j + 3 < end; j += 4) {
        int s0 = csr[j], s1 = csr[j + 1], s2 = csr[j + 2], s3 = csr[j + 3];
        uint4 h0 = *(const uint4*)(hh + (size_t)s0 * FD + lo8);
        uint4 l0 = *(const uint4*)(hl + (size_t)s0 * FD + lo8);
        uint4 h1 = *(const uint4*)(hh + (size_t)s1 * FD + lo8);
        uint4 l1 = *(const uint4*)(hl + (size_t)s1 * FD + lo8);
        uint4 h2 = *(const uint4*)(hh + (size_t)s2 * FD + lo8);
        uint4 l2 = *(const uint4*)(hl + (size_t)s2 * FD + lo8);
        uint4 h3 = *(const uint4*)(hh + (size_t)s3 * FD + lo8);
        uint4 l3 = *(const uint4*)(hl + (size_t)s3 * FD + lo8);
        ACC8(h0, l0);
        ACC8(h1, l1);
        ACC8(h2, l2);
        ACC8(h3, l3);
    }
    for (; j < end; j++) {
        int s0 = csr[j];
        uint4 h0 = *(const uint4*)(hh + (size_t)s0 * FD + lo8);
        uint4 l0 = *(const uint4*)(hl + (size_t)s0 * FD + lo8);
        ACC8(h0, l0);
    }
    int d = end - beg;
    float inv = 1.f / (float)(d > 0 ? d : 1);

    u16 sh[8], sl[8];
    #pragma unroll
    for (int i = 0; i < 8; i++) splith(acc[i] * inv, sh[i], sl[i]);
    uint4 vh, vl;
    vh.x = packh(sh[0], sh[1]); vl.x = packh(sl[0], sl[1]);
    vh.y = packh(sh[2], sh[3]); vl.y = packh(sl[2], sl[3]);
    vh.z = packh(sh[4], sh[5]); vl.z = packh(sl[4], sl[5]);
    vh.w = packh(sh[6], sh[7]); vl.w = packh(sl[6], sl[7]);
    *(uint4*)(oh + (size_t)w * FD + lo8) = vh;
    *(uint4*)(ol + (size_t)w * FD + lo8) = vl;
}

// ---------------------------------------------------------------------------
// Row L2 normalize on planes. If of != null, write fp32 there instead.
// ---------------------------------------------------------------------------
__global__ void norm_pl(const u16* __restrict__ th, const u16* __restrict__ tl,
                        u16* __restrict__ oh, u16* __restrict__ ol,
                        float* __restrict__ of, int n) {
    int w = (blockIdx.x * blockDim.x + threadIdx.x) >> 5;
    int lane = threadIdx.x & 31;
    if (w >= n) return;
    size_t lo8 = (size_t)lane * 8;
    uint4 hv = *(const uint4*)(th + (size_t)w * FD + lo8);
    uint4 lv = *(const uint4*)(tl + (size_t)w * FD + lo8);
    float x[8];
    {
        float2 a = h22f2(hv.x), b = h22f2(lv.x);
        x[0] = a.x + b.x; x[1] = a.y + b.y;
        a = h22f2(hv.y); b = h22f2(lv.y);
        x[2] = a.x + b.x; x[3] = a.y + b.y;
        a = h22f2(hv.z); b = h22f2(lv.z);
        x[4] = a.x + b.x; x[5] = a.y + b.y;
        a = h22f2(hv.w); b = h22f2(lv.w);
        x[6] = a.x + b.x; x[7] = a.y + b.y;
    }
    float s = 0.f;
    #pragma unroll
    for (int i = 0; i < 8; i++) s += x[i] * x[i];
    #pragma unroll
    for (int o = 16; o; o >>= 1) s += __shfl_xor_sync(0xFFFFFFFFu, s, o);
    float inv = 1.f / fmaxf(sqrtf(s), 1e-6f);
    #pragma unroll
    for (int i = 0; i < 8; i++) x[i] *= inv;

    if (of) {
        float4 a = make_float4(x[0], x[1], x[2], x[3]);
        float4 b = make_float4(x[4], x[5], x[6], x[7]);
        *(float4*)(of + (size_t)w * FD + lo8)     = a;
        *(float4*)(of + (size_t)w * FD + lo8 + 4) = b;
    } else {
        u16 sh[8], sl[8];
        #pragma unroll
        for (int i = 0; i < 8; i++) splith(x[i], sh[i], sl[i]);
        uint4 vh, vl;
        vh.x = packh(sh[0], sh[1]); vl.x = packh(sl[0], sl[1]);
        vh.y = packh(sh[2], sh[3]); vl.y = packh(sl[2], sl[3]);
        vh.z = packh(sh[4], sh[5]); vl.z = packh(sl[4], sl[5]);
        vh.w = packh(sh[6], sh[7]); vl.w = packh(sl[6], sl[7]);
        *(uint4*)(oh + (size_t)w * FD + lo8) = vh;
        *(uint4*)(ol + (size_t)w * FD + lo8) = vl;
    }
}

// ---------------------------------------------------------------------------
// Plane GEMM (split-fp16 A, fp16 B, 2-pass: Ah*B + Al*B, fp32 accum):
//   C[m,n] = act( sum_k A[m,k]*B[n,k] + bias[n] ) (+ addin) -> hi/lo planes
// A concat: k < K0 from (Ah,Al) stride K0; k >= K0 from (A2h,A2l) stride K-K0.
// B single fp16 plane, stride K. Tile 128x128, K-chunk 32, 3-stage cp.async
// pipeline. SMEM tiles: 128 rows x 32 fp16, row stride 80B (conflict-free
// ldmatrix). GSM=92160 -> 2 CTAs/SM; __launch_bounds__(256,2) pins regs.
// OOB rows: pointer clamped in-bounds, cp.async zfill writes zeros.
// ---------------------------------------------------------------------------
#define TS    10240            // one tile: 128*80 bytes
#define STG3  (3 * TS)         // Ah, Al, B per stage = 30720
#define GSM   (3 * STG3)       // 92160 bytes dynamic smem (3 stages)
#define ROWB  80

__global__ void __launch_bounds__(256, 2)
pgemm(const u16* __restrict__ Ah, const u16* __restrict__ Al,
      const u16* __restrict__ A2h, const u16* __restrict__ A2l, int K0,
      const u16* __restrict__ Bq,
      const float* __restrict__ bias,
      const u16* __restrict__ addh, const u16* __restrict__ addl,
      u16* __restrict__ Ch, u16* __restrict__ Cl, int Cs,
      int M, int Nn, int K, int do_lrelu) {
    extern __shared__ char smc[];
    u32 smb = smem_u32(smc);
    int tid = threadIdx.x;
    int wid = tid >> 5;
    int lane = tid & 31;
    int block_m = blockIdx.y * 128;
    int block_n = blockIdx.x * 128;
    int nchunk = K >> 5;

    // ---- staging lambda: chunk ch -> stage s (3 tiles: Ah, Al, B) ----
    auto stage = [&](int s, int ch) {
        int k0 = ch << 5;
        const u16 *aH, *aL;
        int ak, astr;
        if (k0 < K0) { aH = Ah;  aL = Al;  ak = k0;      astr = K0; }
        else         { aH = A2h; aL = A2l; ak = k0 - K0; astr = K - K0; }
        for (int e = tid; e < 1536; e += 256) {
            int tile = e >> 9;          // 0..2
            int r = (e >> 2) & 127;
            int c = e & 3;
            const u16* g;
            int valid;
            if (tile < 2) {
                int gm = block_m + r;
                valid = gm < M;
                int gms = valid ? gm : (M - 1);
                g = (tile ? aL : aH) + (size_t)gms * astr + ak + c * 8;
            } else {
                int gn = block_n + r;
                valid = gn < Nn;
                int gns = valid ? gn : (Nn - 1);
                g = Bq + (size_t)gns * K + k0 + c * 8;
            }
            u32 d = smb + s * STG3 + tile * TS + r * ROWB + c * 16;
            cp16(d, g, valid);
        }
    };

    // ---- per-lane ldmatrix offsets ----
    int wm = wid >> 2;   // 0..1
    int wn = wid & 3;    // 0..3
    int lrow = lane & 7;
    int lsel = lane >> 3;
    u32 a_off[4], b_off[2];
    #pragma unroll
    for (int mf = 0; mf < 4; mf++)
        a_off[mf] = (u32)((wm * 64 + mf * 16 + (lsel & 1) * 8 + lrow) * ROWB + (lsel >> 1) * 16);
    #pragma unroll
    for (int nb = 0; nb < 2; nb++)
        b_off[nb] = (u32)((wn * 32 + nb * 16 + (lsel >> 1) * 8 + lrow) * ROWB + (lsel & 1) * 16);

    float acc[4][4][4];
    #pragma unroll
    for (int i = 0; i < 4; i++)
        #pragma unroll
        for (int j = 0; j < 4; j++)
            #pragma unroll
            for (int q = 0; q < 4; q++) acc[i][j][q] = 0.f;

    // ---- 3-stage pipeline ----
    stage(0, 0);
    asm volatile("cp.async.commit_group;");
    if (nchunk > 1) {
        stage(1, 1);
        asm volatile("cp.async.commit_group;");
    }

    for (int ch = 0; ch < nchunk; ch++) {
        if (ch < nchunk - 1) {
            asm volatile("cp.async.wait_group 1;");
        } else {
            asm volatile("cp.async.wait_group 0;");
        }
        __syncthreads();

        // prefetch chunk ch+2 into buffer (ch+2)%3 (freed by the sync above)
        if (ch + 2 < nchunk) {
            stage((ch + 2) % 3, ch + 2);
            asm volatile("cp.async.commit_group;");
        }

        int s = ch % 3;
        u32 bAH = smb + s * STG3;
        u32 bAL = bAH + TS;
        u32 bB  = bAH + 2 * TS;

        #pragma unroll
        for (int ks = 0; ks < 2; ks++) {
            u32 kb = (u32)(ks * 32);
            u32 ah[4][4], al[4][4], b[4][2];
            #pragma unroll
            for (int mf = 0; mf < 4; mf++) {
                ldsm_x4(ah[mf][0], ah[mf][1], ah[mf][2], ah[mf][3], bAH + a_off[mf] + kb);
                ldsm_x4(al[mf][0], al[mf][1], al[mf][2], al[mf][3], bAL + a_off[mf] + kb);
            }
            #pragma unroll
            for (int nb = 0; nb < 2; nb++) {
                u32 r0, r1, r2, r3;
                ldsm_x4(r0, r1, r2, r3, bB + b_off[nb] + kb);
                b[2 * nb][0] = r0; b[2 * nb][1] = r1;
                b[2 * nb + 1][0] = r2; b[2 * nb + 1][1] = r3;
            }
            #pragma unroll
            for (int mf = 0; mf < 4; mf++) {
                #pragma unroll
                for (int nf = 0; nf < 4; nf++) {
                    mma16816(acc[mf][nf], ah[mf][0], ah[mf][1], ah[mf][2], ah[mf][3],
                             b[nf][0], b[nf][1]);
                    mma16816(acc[mf][nf], al[mf][0], al[mf][1], al[mf][2], al[mf][3],
                             b[nf][0], b[nf][1]);
                }
            }
        }
        __syncthreads();
    }

    // ---- epilogue: bias + lrelu + addin, split to fp16 hi/lo planes ----
    int gr = lane >> 2;
    int gc = 2 * (lane & 3);
    #pragma unroll
    for (int mf = 0; mf < 4; mf++) {
        #pragma unroll
        for (int half = 0; half < 2; half++) {
            int gm = block_m + wm * 64 + mf * 16 + gr + half * 8;
            if (gm >= M) continue;
            #pragma unroll
            for (int nf = 0; nf < 4; nf++) {
                int gn = block_n + wn * 32 + nf * 8 + gc;
                if (gn >= Nn) continue;   // Nn even, gn even -> gn+1 < Nn too
                float a0 = acc[mf][nf][half * 2 + 0] + bias[gn];
                float a1 = acc[mf][nf][half * 2 + 1] + bias[gn + 1];
                if (do_lrelu) {
                    a0 = (a0 >= 0.f) ? a0 : 0.1f * a0;
                    a1 = (a1 >= 0.f) ? a1 : 0.1f * a1;
                }
                if (addh) {
                    size_t ai = (size_t)gm * Nn + gn;
                    float2 avh = h22f2(*(const u32*)(addh + ai));
                    float2 avl = h22f2(*(const u32*)(addl + ai));
                    a0 += avh.x + avl.x;
                    a1 += avh.y + avl.y;
                }
                u16 h0, l0, h1, l1;
                splith(a0, h0, l0);
                splith(a1, h1, l1);
                size_t ci = (size_t)gm * Cs + gn;
                *(u32*)(Ch + ci) = packh(h0, h1);
                *(u32*)(Cl + ci) = packh(l0, l1);
            }
        }
    }
}

// ---------------------------------------------------------------------------
// Host driver
// ---------------------------------------------------------------------------
static inline dim3 pg_grid(int M, int Nn) {
    return dim3((Nn + 127) / 128, (M + 127) / 128);
}

extern "C" void kernel_launch(void* const* d_in, const int* in_sizes, int n_in,
                              void* d_out, int out_size) {
    const int*   node_ids = (const int*)  d_in[0];
    const float* content  = (const float*)d_in[1];
    const int*   src      = (const int*)  d_in[2];
    const int*   dst      = (const int*)  d_in[3];
    const float* emb      = (const float*)d_in[4];
    const float* W_exp    = (const float*)d_in[5];
    const float* b_exp    = (const float*)d_in[6];
    const float* W_p1     = (const float*)d_in[7];
    const float* b_p1     = (const float*)d_in[8];
    const float* W_p2     = (const float*)d_in[9];
    const float* b_p2     = (const float*)d_in[10];
    const float* W_conv   = (const float*)d_in[11];
    const float* b_conv   = (const float*)d_in[12];
    const float* Wo1      = (const float*)d_in[13];
    const float* bo1      = (const float*)d_in[14];
    const float* Wo2      = (const float*)d_in[15];
    const float* bo2      = (const float*)d_in[16];
    float* out = (float*)d_out;

    const int N = in_sizes[0];
    const int E = in_sizes[2];

    u16 *conth, *contl, *ch_, *cl_, *eh_, *el_, *hh_, *hl_, *th_, *tl_, *gh_, *gl_, *wq_;
    int *p_deg, *p_off, *p_cur, *p_csr;
    cudaGetSymbolAddress((void**)&conth, g_cont_h);  cudaGetSymbolAddress((void**)&contl, g_cont_l);
    cudaGetSymbolAddress((void**)&ch_,   g_c_h);     cudaGetSymbolAddress((void**)&cl_,   g_c_l);
    cudaGetSymbolAddress((void**)&eh_,   g_e_h);     cudaGetSymbolAddress((void**)&el_,   g_e_l);
    cudaGetSymbolAddress((void**)&hh_,   g_h_h);     cudaGetSymbolAddress((void**)&hl_,   g_h_l);
    cudaGetSymbolAddress((void**)&th_,   g_t_h);     cudaGetSymbolAddress((void**)&tl_,   g_t_l);
    cudaGetSymbolAddress((void**)&gh_,   g_g_h);     cudaGetSymbolAddress((void**)&gl_,   g_g_l);
    cudaGetSymbolAddress((void**)&wq_,   g_w);
    cudaGetSymbolAddress((void**)&p_deg, g_deg);     cudaGetSymbolAddress((void**)&p_off, g_off);
    cudaGetSymbolAddress((void**)&p_cur, g_cur);     cudaGetSymbolAddress((void**)&p_csr, g_csr);

    cudaFuncSetAttribute(pgemm, cudaFuncAttributeMaxDynamicSharedMemorySize, GSM);

    // ---- CSR build ----
    zero_int_kernel<<<(N + 255) / 256, 256>>>(p_deg, N);
    deg_kernel<<<(E + 255) / 256, 256>>>(dst, p_deg, E);
    scan_kernel<<<1, 1024>>>(p_deg, p_off, p_cur, N);
    fill_kernel<<<(E + 255) / 256, 256>>>(src, dst, p_cur, p_csr, E);

    // ---- split inputs to planes ----
    {
        int n1 = N * NCP;
        splita_kernel<<<(n1 + 255) / 256, 256>>>(content, N, NC, NCP, conth, contl, nullptr);
        int n2 = N * ED;
        splita_kernel<<<(n2 + 255) / 256, 256>>>(emb, N, ED, ED, eh_, el_, node_ids);
        splitw_kernel<<<(300 * NCP + 255) / 256, 256>>>(W_p1, 300, NC, NCP, wq_ + WP1);
        splitw_kernel<<<(256 * NCP + 255) / 256, 256>>>(W_p2, 256, NC, NCP, wq_ + WP2);
        splitw_kernel<<<(256 * 64 + 255) / 256, 256>>>(W_exp, 256, 64, 64, wq_ + WEXP);
        splitw_kernel<<<(768 * 512 + 255) / 256, 256>>>(W_conv, 768, 512, 512, wq_ + WCONV);
        splitw_kernel<<<(512 * 256 + 255) / 256, 256>>>(Wo1, 512, 256, 256, wq_ + WO1);
        splitw_kernel<<<(512 * 256 + 255) / 256, 256>>>(Wo2, 512, 256, 256, wq_ + WO2);
    }

    // ---- initial node representation ----
    // c = lrelu(content @ W_p1^T + b_p1)   [N,300] (Cs=320)
    pgemm<<<pg_grid(N, NC), 256, GSM>>>(conth, contl, conth, contl, NCP,
                                        wq_ + WP1, b_p1,
                                        nullptr, nullptr,
                                        ch_, cl_, NCP, N, NC, NCP, 1);
    // t = lrelu(c @ W_p2^T + b_p2)         [N,256]
    pgemm<<<pg_grid(N, FD), 256, GSM>>>(ch_, cl_, ch_, cl_, NCP,
                                        wq_ + WP2, b_p2,
                                        nullptr, nullptr,
                                        th_, tl_, FD, N, FD, NCP, 1);
    // h = lrelu(emb[ids] @ W_exp^T + b_exp) + t
    pgemm<<<pg_grid(N, FD), 256, GSM>>>(eh_, el_, eh_, el_, ED,
                                        wq_ + WEXP, b_exp,
                                        th_, tl_,
                                        hh_, hl_, FD, N, FD, ED, 1);

    const int warp_blocks = (N * 32 + 255) / 256;

    // ---- 3 SAGE layers ----
    for (int i = 0; i < 3; i++) {
        agg_pl<<<warp_blocks, 256>>>(hh_, hl_, p_off, p_csr, gh_, gl_, N);
        // t = (lrelu?)( [h, h_agg] @ W_conv[i]^T + b_conv[i] )
        pgemm<<<pg_grid(N, FD), 256, GSM>>>(hh_, hl_, gh_, gl_, FD,
                                            wq_ + WCONV + (size_t)i * FD * 2 * FD,
                                            b_conv + (size_t)i * FD,
                                            nullptr, nullptr,
                                            th_, tl_, FD, N, FD, 2 * FD, (i < 2) ? 1 : 0);
        if (i < 2) {
            norm_pl<<<warp_blocks, 256>>>(th_, tl_, th_, tl_, nullptr, N);
            pgemm<<<pg_grid(N, FD), 256, GSM>>>(th_, tl_, th_, tl_, FD,
                                                wq_ + WO1 + (size_t)i * FD * FD,
                                                bo1 + (size_t)i * FD,
                                                nullptr, nullptr,
                                                gh_, gl_, FD, N, FD, FD, 1);
            pgemm<<<pg_grid(N, FD), 256, GSM>>>(gh_, gl_, gh_, gl_, FD,
                                                wq_ + WO2 + (size_t)i * FD * FD,
                                                bo2 + (size_t)i * FD,
                                                nullptr, nullptr,
                                                hh_, hl_, FD, N, FD, FD, 0);
        } else {
            norm_pl<<<warp_blocks, 256>>>(th_, tl_, nullptr, nullptr, out, N);
        }
    }
}